// round 15
// baseline (speedup 1.0000x reference)
#include <cuda_runtime.h>
#include <cuda_bf16.h>

// HXELoss: B=256 rows, C=4096 classes, 8-ary tree depth 4.
// per_sample(b) = sum_j w[t,j]*(log E_{8^(j+1)} - log E_{8^j}); Z & max cancel.
//
// MUFU.EX2 roofline (14.2K cyc/SM) is the measured bind. Attack: dual-pipe exp.
//  - warps 0-3: __expf (FMUL+MUFU.EX2) for all their elements.
//  - warps 4-7: MUFU-free exp on the FMA pipe via packed fma.rn.f32x2:
//      y = x*log2e; s = RN(y+12582912); k = s-magic; f = y-k (|f|<=0.5);
//      p = deg4-Taylor 2^f;  result_bits = p_bits + (s_bits<<23)
//      (low 9 bits of magic's bit pattern are 0 -> (s_bits<<23) == k<<23 mod 2^32).
//    ~8 f32x2 ops/pair on fma pipe + 2 alu ops/elem; rel err <= 6e-5, feeds only
//    large averaged sums (bias cancels in log ratios).
//  - the target's iteration (i == t9>>1) stays full-f32 __expf in all warps so
//    E_8/E_64/e_t come from precise values. All branches warp-uniform.
// Each SMSP hosts 1 MUFU warp + 1 poly warp (wid<4 vs >=4; wid%4 = SMSP).
//
// Shell unchanged from R10: 256 CTAs x 256 thr, 1 row/CTA, acq_rel ticket,
// last CTA fixed-order mean. Targets int32 on device.

#define Bn  256
#define Cn  4096
#define TPB 256
#define VPT 4
#define L2E 1.4426950408889634f

__device__ float        g_partial[Bn];
__device__ unsigned int g_count = 0;

__device__ __forceinline__ float warpSum(float x) {
#pragma unroll
    for (int o = 16; o > 0; o >>= 1) x += __shfl_xor_sync(0xffffffffu, x, o);
    return x;
}

// ---- packed f32x2 helpers ----
__device__ __forceinline__ unsigned long long pk2(float a, float b) {
    unsigned long long r;
    asm("mov.b64 %0, {%1, %2};" : "=l"(r) : "f"(a), "f"(b));
    return r;
}
__device__ __forceinline__ void upk2i(unsigned long long x, int& a, int& b) {
    asm("mov.b64 {%0, %1}, %2;" : "=r"(a), "=r"(b) : "l"(x));
}
__device__ __forceinline__ unsigned long long mul2(unsigned long long a, unsigned long long b) {
    unsigned long long r;
    asm("mul.rn.f32x2 %0, %1, %2;" : "=l"(r) : "l"(a), "l"(b));
    return r;
}
__device__ __forceinline__ unsigned long long add2(unsigned long long a, unsigned long long b) {
    unsigned long long r;
    asm("add.rn.f32x2 %0, %1, %2;" : "=l"(r) : "l"(a), "l"(b));
    return r;
}
__device__ __forceinline__ unsigned long long fma2(unsigned long long a, unsigned long long b,
                                                   unsigned long long c) {
    unsigned long long r;
    asm("fma.rn.f32x2 %0, %1, %2, %3;" : "=l"(r) : "l"(a), "l"(b), "l"(c));
    return r;
}

// exp of a packed pair via FMA pipe only; returns the two exps as floats.
__device__ __forceinline__ void exp2pair(unsigned long long v,
                                         unsigned long long L2E2,
                                         unsigned long long MG2,
                                         unsigned long long NMG2,
                                         unsigned long long N1_2,
                                         unsigned long long C4_2,
                                         unsigned long long C3_2,
                                         unsigned long long C2_2,
                                         unsigned long long C1_2,
                                         unsigned long long C0_2,
                                         float& r0, float& r1)
{
    const unsigned long long y = mul2(v, L2E2);
    const unsigned long long s = add2(y, MG2);      // RN(y + magic)
    const unsigned long long k = add2(s, NMG2);     // exact k
    const unsigned long long f = fma2(k, N1_2, y);  // y - k, |f| <= 0.5
    unsigned long long p = fma2(f, C4_2, C3_2);
    p = fma2(f, p, C2_2);
    p = fma2(f, p, C1_2);
    p = fma2(f, p, C0_2);                           // 2^f
    int s0, s1, p0, p1;
    upk2i(s, s0, s1);
    upk2i(p, p0, p1);
    r0 = __int_as_float(p0 + (s0 << 23));           // 2^f * 2^k
    r1 = __int_as_float(p1 + (s1 << 23));
}

__global__ __launch_bounds__(TPB) void hxe_fused(
    const float* __restrict__ logits,
    const int* __restrict__ tgt,
    const float* __restrict__ weights,
    float* __restrict__ out)
{
    const int b   = blockIdx.x;
    const int tid = threadIdx.x;
    const int wid = tid >> 5;
    const int lid = tid & 31;

    const float4* row4 = (const float4*)(logits + (size_t)b * Cn);

    // ---- target & block ids (int32 storage!) ----
    const int t  = tgt[b * 4 + 3];
    const int t2 = t >> 2;
    const int t3 = t >> 3;
    const int t6 = t >> 6;
    const int t9 = t >> 9;
    const int tk = t & 3;
    const int tIter = t9 >> 1;           // iteration containing the 512-block

    // packed constants (deg-4 Taylor of 2^f)
    const unsigned long long L2E2 = pk2(L2E, L2E);
    const unsigned long long MG2  = pk2(12582912.0f, 12582912.0f);
    const unsigned long long NMG2 = pk2(-12582912.0f, -12582912.0f);
    const unsigned long long N1_2 = pk2(-1.0f, -1.0f);
    const unsigned long long C4_2 = pk2(0.009618129f, 0.009618129f);
    const unsigned long long C3_2 = pk2(0.055504109f, 0.055504109f);
    const unsigned long long C2_2 = pk2(0.240226507f, 0.240226507f);
    const unsigned long long C1_2 = pk2(0.693147181f, 0.693147181f);
    const unsigned long long C0_2 = pk2(1.0f, 1.0f);

    // ---- load row (float4, coalesced, front-batched) ----
    float4 v[VPT];
#pragma unroll
    for (int i = 0; i < VPT; i++) v[i] = row4[tid + i * TPB];

    // ---- exp-block sums, dual-pipe ----
    float et = 0.f, e8 = 0.f, e64 = 0.f, e512 = 0.f, Z = 0.f;
#pragma unroll
    for (int i = 0; i < VPT; i++) {
        const int g = tid + i * TPB;     // classes 4g..4g+3
        const bool polyWarp = (wid >= 4) && (i != tIter);   // warp-uniform
        if (polyWarp) {
            // MUFU-free path: FMA pipe (fma.rn.f32x2) + ALU bit-assembly
            float r0, r1, r2, r3;
            exp2pair(pk2(v[i].x, v[i].y), L2E2, MG2, NMG2, N1_2,
                     C4_2, C3_2, C2_2, C1_2, C0_2, r0, r1);
            exp2pair(pk2(v[i].z, v[i].w), L2E2, MG2, NMG2, N1_2,
                     C4_2, C3_2, C2_2, C1_2, C0_2, r2, r3);
            Z += (r0 + r1) + (r2 + r3);
        } else {
            const float e0 = __expf(v[i].x);
            const float e1 = __expf(v[i].y);
            const float e2 = __expf(v[i].z);
            const float e3 = __expf(v[i].w);
            const float s4 = (e0 + e1) + (e2 + e3);
            Z += s4;
            if (i == tIter && (g >> 7) == t9) {   // warp-uniform
                e512 += s4;
                const int c = g << 2;
                if ((c >> 6) == t6) {
                    e64 += s4;
                    if ((c >> 3) == t3) {
                        e8 += s4;
                        if (g == t2) et = (tk == 0) ? e0 : (tk == 1) ? e1
                                        : (tk == 2) ? e2 : e3;
                    }
                }
            }
        }
    }

    // ---- block reduce the 5 partials (8 warps) ----
    __shared__ float rs[8][5];
    et   = warpSum(et);
    e8   = warpSum(e8);
    e64  = warpSum(e64);
    e512 = warpSum(e512);
    Z    = warpSum(Z);
    if (lid == 0) {
        rs[wid][0] = et; rs[wid][1] = e8; rs[wid][2] = e64;
        rs[wid][3] = e512; rs[wid][4] = Z;
    }
    __syncthreads();

    __shared__ bool isLast;
    if (tid == 0) {
        float s[5] = {0.f, 0.f, 0.f, 0.f, 0.f};
#pragma unroll
        for (int w = 0; w < 8; w++)
#pragma unroll
            for (int k = 0; k < 5; k++) s[k] += rs[w][k];

        float per = 0.f;
#pragma unroll
        for (int j = 0; j < 4; j++) {
            const float numj = s[j], denj = s[j + 1];
            if (numj != 0.f)
                per += weights[t * 4 + j] * (__logf(denj) - __logf(numj));
        }
        g_partial[b] = per;

        unsigned int ticket;
        asm volatile("atom.acq_rel.gpu.global.inc.u32 %0, [%1], %2;"
                     : "=r"(ticket)
                     : "l"(&g_count), "r"((unsigned)(Bn - 1))
                     : "memory");
        isLast = (ticket == Bn - 1);
    }
    __syncthreads();

    // ---- last CTA: deterministic fixed-order batch mean ----
    if (isLast) {
        float x = __ldcg(&g_partial[tid]);
        x = warpSum(x);
        __shared__ float red[8];
        if (lid == 0) red[wid] = x;
        __syncthreads();
        if (tid < 32) {
            float s = (lid < 8) ? red[lid] : 0.f;
            s = warpSum(s);
            if (lid == 0) out[0] = s * (1.0f / (float)Bn);
        }
    }
}

extern "C" void kernel_launch(void* const* d_in, const int* in_sizes, int n_in,
                              void* d_out, int out_size)
{
    const float* logits  = (const float*)d_in[0];
    const int*   tgt     = (const int*)d_in[1];
    // d_in[2] = onehot_num, d_in[3] = onehot_den  -- structural, unused.
    const float* weights = (const float*)d_in[4];
    float*       out     = (float*)d_out;

    hxe_fused<<<Bn, TPB>>>(logits, tgt, weights, out);
}